// round 1
// baseline (speedup 1.0000x reference)
#include <cuda_runtime.h>
#include <math.h>

// Problem dims (fixed by the reference)
static constexpr int BATCH = 4;
static constexpr int SEQ   = 4096;
static constexpr int DIM   = 1024;   // d_in == d_new
static constexpr int MTOT  = BATCH * SEQ;  // 16384 rows for projection

// Scratch (device globals — no allocation allowed)
__device__ float g_Q[(size_t)BATCH * SEQ * DIM];
__device__ float g_K[(size_t)BATCH * SEQ * DIM];
__device__ float g_V[(size_t)BATCH * SEQ * DIM];
__device__ float g_S[(size_t)BATCH * SEQ * SEQ];

// ---------------------------------------------------------------------------
// Tiled SGEMM: C = alpha * A @ op(B) + bias
//   A: [M, Kd] row-major (lda = Kd)
//   TRANSB == 0:  B: [Kd, Nc] row-major (ldb = Nc)   -> C = A @ B
//   TRANSB == 1:  B: [Nc, Kd] row-major (ldb = Kd)   -> C = A @ B^T
//   C: [M, Nc] row-major (ldc = Nc)
//   Batched over blockIdx.z with element strides sA, sB, sC.
//   All dims must be multiples of the tile sizes (true for this problem).
// ---------------------------------------------------------------------------
template <int TRANSB>
__global__ __launch_bounds__(256)
void sgemm_kernel(const float* __restrict__ A,
                  const float* __restrict__ B,
                  float* __restrict__ C,
                  const float* __restrict__ bias,   // may be nullptr
                  int M, int Nc, int Kd,
                  long long sA, long long sB, long long sC,
                  float alpha)
{
    constexpr int BM = 128, BN = 128, BK = 8, TM = 8, TN = 8;

    __shared__ float As[BK][BM];
    __shared__ float Bs[BK][BN];

    A += (long long)blockIdx.z * sA;
    B += (long long)blockIdx.z * sB;
    C += (long long)blockIdx.z * sC;

    const int tid = threadIdx.x;                 // 0..255
    const int block_row = blockIdx.y;            // tile row in M
    const int block_col = blockIdx.x;            // tile col in Nc

    const int trow = tid / (BN / TN);            // 0..15
    const int tcol = tid % (BN / TN);            // 0..15

    // A-tile load coords: 128 rows x 8 cols, one float4 per thread
    const int a_row = tid >> 1;                  // 0..127
    const int a_col = (tid & 1) * 4;             // 0 or 4

    // B-tile load coords
    // TRANSB==0: tile is [BK x BN] = 8 x 128, float4 along Nc
    const int b_row_nn = tid >> 5;               // 0..7   (k)
    const int b_col_nn = (tid & 31) * 4;         // 0..124 (n)
    // TRANSB==1: tile is [BN x BK] = 128 x 8 from B rows, float4 along Kd
    const int b_row_nt = tid >> 1;               // 0..127 (n local)
    const int b_col_nt = (tid & 1) * 4;          // 0 or 4 (k)

    const float* Ab = A + (long long)block_row * BM * Kd;

    float acc[TM][TN];
#pragma unroll
    for (int i = 0; i < TM; i++)
#pragma unroll
        for (int j = 0; j < TN; j++) acc[i][j] = 0.0f;

    for (int k0 = 0; k0 < Kd; k0 += BK) {
        // Load A tile (transpose into As[k][m])
        {
            float4 av = *(const float4*)(Ab + (long long)a_row * Kd + k0 + a_col);
            As[a_col + 0][a_row] = av.x;
            As[a_col + 1][a_row] = av.y;
            As[a_col + 2][a_row] = av.z;
            As[a_col + 3][a_row] = av.w;
        }
        // Load B tile
        if (TRANSB == 0) {
            const float* Bb = B + (long long)(k0 + b_row_nn) * Nc
                                + (long long)block_col * BN + b_col_nn;
            *(float4*)&Bs[b_row_nn][b_col_nn] = *(const float4*)Bb;
        } else {
            const float* Bb = B + (long long)(block_col * BN + b_row_nt) * Kd
                                + k0 + b_col_nt;
            float4 bv = *(const float4*)Bb;
            Bs[b_col_nt + 0][b_row_nt] = bv.x;
            Bs[b_col_nt + 1][b_row_nt] = bv.y;
            Bs[b_col_nt + 2][b_row_nt] = bv.z;
            Bs[b_col_nt + 3][b_row_nt] = bv.w;
        }
        __syncthreads();

#pragma unroll
        for (int k = 0; k < BK; k++) {
            float4 a0 = *(const float4*)&As[k][trow * TM];
            float4 a1 = *(const float4*)&As[k][trow * TM + 4];
            float4 b0 = *(const float4*)&Bs[k][tcol * TN];
            float4 b1 = *(const float4*)&Bs[k][tcol * TN + 4];
            float ar[TM] = {a0.x, a0.y, a0.z, a0.w, a1.x, a1.y, a1.z, a1.w};
            float br[TN] = {b0.x, b0.y, b0.z, b0.w, b1.x, b1.y, b1.z, b1.w};
#pragma unroll
            for (int i = 0; i < TM; i++)
#pragma unroll
                for (int j = 0; j < TN; j++)
                    acc[i][j] = fmaf(ar[i], br[j], acc[i][j]);
        }
        __syncthreads();
    }

    // Epilogue
    const int col0 = block_col * BN + tcol * TN;
    float bv[TN];
#pragma unroll
    for (int j = 0; j < TN; j++)
        bv[j] = bias ? bias[col0 + j] : 0.0f;

#pragma unroll
    for (int i = 0; i < TM; i++) {
        const long long row = (long long)block_row * BM + trow * TM + i;
        float4 o0, o1;
        o0.x = acc[i][0] * alpha + bv[0];
        o0.y = acc[i][1] * alpha + bv[1];
        o0.z = acc[i][2] * alpha + bv[2];
        o0.w = acc[i][3] * alpha + bv[3];
        o1.x = acc[i][4] * alpha + bv[4];
        o1.y = acc[i][5] * alpha + bv[5];
        o1.z = acc[i][6] * alpha + bv[6];
        o1.w = acc[i][7] * alpha + bv[7];
        *(float4*)(C + row * Nc + col0)     = o0;
        *(float4*)(C + row * Nc + col0 + 4) = o1;
    }
}

// ---------------------------------------------------------------------------
// Row softmax, in place. One block per row, 256 threads, row length n.
// ---------------------------------------------------------------------------
__global__ __launch_bounds__(256)
void softmax_rows_kernel(float* __restrict__ S, int n)
{
    const int tid = threadIdx.x;
    float* p = S + (size_t)blockIdx.x * n;

    __shared__ float red[256];

    // max
    float m = -INFINITY;
    for (int i = tid; i < n; i += 256) m = fmaxf(m, p[i]);
    red[tid] = m;
    __syncthreads();
    for (int s = 128; s > 0; s >>= 1) {
        if (tid < s) red[tid] = fmaxf(red[tid], red[tid + s]);
        __syncthreads();
    }
    m = red[0];
    __syncthreads();

    // exp + sum
    float sum = 0.0f;
    for (int i = tid; i < n; i += 256) {
        float e = __expf(p[i] - m);
        p[i] = e;
        sum += e;
    }
    red[tid] = sum;
    __syncthreads();
    for (int s = 128; s > 0; s >>= 1) {
        if (tid < s) red[tid] += red[tid + s];
        __syncthreads();
    }
    const float inv = 1.0f / red[0];
    __syncthreads();

    for (int i = tid; i < n; i += 256) p[i] *= inv;
}

// ---------------------------------------------------------------------------
extern "C" void kernel_launch(void* const* d_in, const int* in_sizes, int n_in,
                              void* d_out, int out_size)
{
    const float* X  = (const float*)d_in[0];
    const float* Wq = (const float*)d_in[1];
    const float* Wk = (const float*)d_in[2];
    const float* Wv = (const float*)d_in[3];
    const float* bq = (const float*)d_in[4];
    const float* bk = (const float*)d_in[5];
    const float* bv = (const float*)d_in[6];
    float* Out = (float*)d_out;

    float *Q, *K, *V, *S;
    cudaGetSymbolAddress((void**)&Q, g_Q);
    cudaGetSymbolAddress((void**)&K, g_K);
    cudaGetSymbolAddress((void**)&V, g_V);
    cudaGetSymbolAddress((void**)&S, g_S);

    const dim3 threads(256);
    const float scale = 0.03125f;  // 1/sqrt(1024)

    // Stage 1: Q/K/V = X @ W + b   (M=16384, N=1024, K=1024)
    {
        dim3 grid(DIM / 128, MTOT / 128, 1);
        sgemm_kernel<0><<<grid, threads>>>(X, Wq, Q, bq, MTOT, DIM, DIM, 0, 0, 0, 1.0f);
        sgemm_kernel<0><<<grid, threads>>>(X, Wk, K, bk, MTOT, DIM, DIM, 0, 0, 0, 1.0f);
        sgemm_kernel<0><<<grid, threads>>>(X, Wv, V, bv, MTOT, DIM, DIM, 0, 0, 0, 1.0f);
    }

    // Stage 2: S_b = scale * Q_b @ K_b^T   (per batch: M=4096, N=4096, K=1024)
    {
        dim3 grid(SEQ / 128, SEQ / 128, BATCH);
        sgemm_kernel<1><<<grid, threads>>>(
            Q, K, S, nullptr, SEQ, SEQ, DIM,
            (long long)SEQ * DIM, (long long)SEQ * DIM, (long long)SEQ * SEQ,
            scale);
    }

    // Stage 3: softmax over last dim of S (16384 rows of length 4096)
    softmax_rows_kernel<<<BATCH * SEQ, threads>>>(S, SEQ);

    // Stage 4: Out_b = P_b @ V_b   (per batch: M=4096, N=1024, K=4096)
    {
        dim3 grid(DIM / 128, SEQ / 128, BATCH);
        sgemm_kernel<0><<<grid, threads>>>(
            S, V, Out, nullptr, SEQ, DIM, SEQ,
            (long long)SEQ * SEQ, (long long)SEQ * DIM, (long long)SEQ * DIM,
            1.0f);
    }
}

// round 2
// speedup vs baseline: 1.2417x; 1.2417x over previous
#include <cuda_runtime.h>
#include <math.h>
#include <stdint.h>

// Problem dims (fixed by the reference)
static constexpr int BATCH = 4;
static constexpr int SEQ   = 4096;
static constexpr int DIM   = 1024;
static constexpr int MTOT  = BATCH * SEQ;

// Scratch (device globals — no allocation allowed)
__device__ float g_Q[(size_t)BATCH * SEQ * DIM];
__device__ float g_K[(size_t)BATCH * SEQ * DIM];
__device__ float g_V[(size_t)BATCH * SEQ * DIM];
__device__ float g_S[(size_t)BATCH * SEQ * SEQ];

// ---------------------------------------------------------------------------
// helpers
// ---------------------------------------------------------------------------
__device__ __forceinline__ uint32_t cvt_tf32(float x) {
    uint32_t u;
    asm("cvt.rna.tf32.f32 %0, %1;" : "=r"(u) : "f"(x));
    return u;
}

__device__ __forceinline__ void mma_tf32(float& d0, float& d1, float& d2, float& d3,
                                         uint32_t a0, uint32_t a1, uint32_t a2, uint32_t a3,
                                         uint32_t b0, uint32_t b1) {
    asm volatile(
        "mma.sync.aligned.m16n8k8.row.col.f32.tf32.tf32.f32 "
        "{%0,%1,%2,%3}, {%4,%5,%6,%7}, {%8,%9}, {%0,%1,%2,%3};\n"
        : "+f"(d0), "+f"(d1), "+f"(d2), "+f"(d3)
        : "r"(a0), "r"(a1), "r"(a2), "r"(a3), "r"(b0), "r"(b1));
}

__device__ __forceinline__ void cp16(uint32_t saddr, const void* gaddr) {
    asm volatile("cp.async.cg.shared.global [%0], [%1], 16;\n"
                 :: "r"(saddr), "l"(gaddr));
}
__device__ __forceinline__ void cp_commit() {
    asm volatile("cp.async.commit_group;\n" ::: "memory");
}
template <int N>
__device__ __forceinline__ void cp_wait() {
    asm volatile("cp.async.wait_group %0;\n" :: "n"(N) : "memory");
}

// ---------------------------------------------------------------------------
// Tensor-core GEMM (tf32x3 split -> fp32 accuracy):
//   C = alpha * A @ op(B) + bias
//   A: [M, Kd] row-major.
//   TRANSB==0: B [Kd, Nc] row-major.  TRANSB==1: B [Nc, Kd] row-major (C=A@B^T).
//   All dims multiples of tile sizes. Batched via blockIdx.z strides.
// ---------------------------------------------------------------------------
template <int TRANSB>
__global__ __launch_bounds__(256, 1)
void mma_gemm(const float* __restrict__ A,
              const float* __restrict__ B,
              float* __restrict__ C,
              const float* __restrict__ bias,
              int M, int Nc, int Kd,
              long long sA, long long sB, long long sC,
              float alpha)
{
    constexpr int BM = 128, BN = 128, BK = 16;
    constexpr int ASTR = 20;                      // conflict-free stride for [row][k] tiles
    constexpr int BSTR = TRANSB ? 20 : 136;       // NT: [n][k] str20; NN: [k][n] str136
    constexpr int BELEMS = TRANSB ? (BN * 20) : (BK * 136);

    __shared__ __align__(16) float As[2][BM * ASTR];
    __shared__ __align__(16) float Bs[2][BELEMS];

    A += (long long)blockIdx.z * sA;
    B += (long long)blockIdx.z * sB;
    C += (long long)blockIdx.z * sC;

    const int tid  = threadIdx.x;
    const int w    = tid >> 5;
    const int lane = tid & 31;
    const int g    = lane >> 2;   // groupID
    const int tg   = lane & 3;    // thread-in-group
    const int wm   = (w & 1) * 64;
    const int wn   = (w >> 1) * 32;

    const long long arow0 = (long long)blockIdx.y * BM;
    const long long bcol0 = (long long)blockIdx.x * BN;

    float acc[4][4][4];
#pragma unroll
    for (int i = 0; i < 4; i++)
#pragma unroll
        for (int j = 0; j < 4; j++)
#pragma unroll
            for (int k = 0; k < 4; k++) acc[i][j][k] = 0.0f;

    const uint32_t sAs0 = (uint32_t)__cvta_generic_to_shared(&As[0][0]);
    const uint32_t sAs1 = (uint32_t)__cvta_generic_to_shared(&As[1][0]);
    const uint32_t sBs0 = (uint32_t)__cvta_generic_to_shared(&Bs[0][0]);
    const uint32_t sBs1 = (uint32_t)__cvta_generic_to_shared(&Bs[1][0]);

    const int Ktiles = Kd / BK;

    // -------- tile loaders (cp.async, 2 x 16B per thread per tile each) -----
    auto load_tile = [&](int buf, int k0) {
        const uint32_t sa = buf ? sAs1 : sAs0;
        const uint32_t sb = buf ? sBs1 : sBs0;
#pragma unroll
        for (int i = 0; i < 2; i++) {
            int c   = tid + i * 256;          // 0..511
            int row = c >> 2;                 // 0..127
            int cc  = (c & 3) * 4;            // 0,4,8,12
            const float* gp = A + (arow0 + row) * Kd + (k0 + cc);
            cp16(sa + (uint32_t)(row * ASTR + cc) * 4u, gp);
        }
#pragma unroll
        for (int i = 0; i < 2; i++) {
            int c = tid + i * 256;
            if (TRANSB) {
                int row = c >> 2;             // local n
                int cc  = (c & 3) * 4;        // k
                const float* gp = B + (bcol0 + row) * Kd + (k0 + cc);
                cp16(sb + (uint32_t)(row * 20 + cc) * 4u, gp);
            } else {
                int row = c >> 5;             // k: 0..15
                int cc  = (c & 31) * 4;       // n: 0..124
                const float* gp = B + (long long)(k0 + row) * Nc + bcol0 + cc;
                cp16(sb + (uint32_t)(row * 136 + cc) * 4u, gp);
            }
        }
        cp_commit();
    };

    // -------- compute one BK=16 tile ---------------------------------------
    auto compute = [&](int buf) {
        const float* As_ = &As[buf][0];
        const float* Bs_ = &Bs[buf][0];
#pragma unroll
        for (int ks = 0; ks < 2; ks++) {
            const int kb = ks * 8;

            uint32_t ah[4][4], al[4][4];
#pragma unroll
            for (int mi = 0; mi < 4; mi++) {
                const int r = wm + mi * 16 + g;
                float a0 = As_[r * ASTR + kb + tg];
                float a1 = As_[(r + 8) * ASTR + kb + tg];
                float a2 = As_[r * ASTR + kb + tg + 4];
                float a3 = As_[(r + 8) * ASTR + kb + tg + 4];
                ah[mi][0] = cvt_tf32(a0); al[mi][0] = cvt_tf32(a0 - __uint_as_float(ah[mi][0]));
                ah[mi][1] = cvt_tf32(a1); al[mi][1] = cvt_tf32(a1 - __uint_as_float(ah[mi][1]));
                ah[mi][2] = cvt_tf32(a2); al[mi][2] = cvt_tf32(a2 - __uint_as_float(ah[mi][2]));
                ah[mi][3] = cvt_tf32(a3); al[mi][3] = cvt_tf32(a3 - __uint_as_float(ah[mi][3]));
            }

            uint32_t bh[4][2], bl[4][2];
#pragma unroll
            for (int ni = 0; ni < 4; ni++) {
                const int n = wn + ni * 8 + g;
                float b0, b1;
                if (TRANSB) {
                    b0 = Bs_[n * 20 + kb + tg];
                    b1 = Bs_[n * 20 + kb + tg + 4];
                } else {
                    b0 = Bs_[(kb + tg) * 136 + n];
                    b1 = Bs_[(kb + tg + 4) * 136 + n];
                }
                bh[ni][0] = cvt_tf32(b0); bl[ni][0] = cvt_tf32(b0 - __uint_as_float(bh[ni][0]));
                bh[ni][1] = cvt_tf32(b1); bl[ni][1] = cvt_tf32(b1 - __uint_as_float(bh[ni][1]));
            }

            // cross terms first, then the main term
#pragma unroll
            for (int mi = 0; mi < 4; mi++)
#pragma unroll
                for (int ni = 0; ni < 4; ni++)
                    mma_tf32(acc[mi][ni][0], acc[mi][ni][1], acc[mi][ni][2], acc[mi][ni][3],
                             al[mi][0], al[mi][1], al[mi][2], al[mi][3],
                             bh[ni][0], bh[ni][1]);
#pragma unroll
            for (int mi = 0; mi < 4; mi++)
#pragma unroll
                for (int ni = 0; ni < 4; ni++)
                    mma_tf32(acc[mi][ni][0], acc[mi][ni][1], acc[mi][ni][2], acc[mi][ni][3],
                             ah[mi][0], ah[mi][1], ah[mi][2], ah[mi][3],
                             bl[ni][0], bl[ni][1]);
#pragma unroll
            for (int mi = 0; mi < 4; mi++)
#pragma unroll
                for (int ni = 0; ni < 4; ni++)
                    mma_tf32(acc[mi][ni][0], acc[mi][ni][1], acc[mi][ni][2], acc[mi][ni][3],
                             ah[mi][0], ah[mi][1], ah[mi][2], ah[mi][3],
                             bh[ni][0], bh[ni][1]);
        }
    };

    // -------- main loop: double-buffered pipeline --------------------------
    load_tile(0, 0);
    for (int kt = 0; kt < Ktiles; kt++) {
        const int cur = kt & 1;
        if (kt + 1 < Ktiles) {
            load_tile(cur ^ 1, (kt + 1) * BK);
            cp_wait<1>();
        } else {
            cp_wait<0>();
        }
        __syncthreads();
        compute(cur);
        __syncthreads();
    }

    // -------- epilogue ------------------------------------------------------
#pragma unroll
    for (int ni = 0; ni < 4; ni++) {
        const int c = (int)bcol0 + wn + ni * 8 + 2 * tg;
        const float bv0 = bias ? bias[c] : 0.0f;
        const float bv1 = bias ? bias[c + 1] : 0.0f;
#pragma unroll
        for (int mi = 0; mi < 4; mi++) {
            const long long r0 = arow0 + wm + mi * 16 + g;
            const long long r1 = r0 + 8;
            float2 v0, v1;
            v0.x = acc[mi][ni][0] * alpha + bv0;
            v0.y = acc[mi][ni][1] * alpha + bv1;
            v1.x = acc[mi][ni][2] * alpha + bv0;
            v1.y = acc[mi][ni][3] * alpha + bv1;
            *(float2*)(C + r0 * Nc + c) = v0;
            *(float2*)(C + r1 * Nc + c) = v1;
        }
    }
}

// ---------------------------------------------------------------------------
// Row softmax, in place. One block per row, 256 threads, row length n.
// ---------------------------------------------------------------------------
__global__ __launch_bounds__(256)
void softmax_rows_kernel(float* __restrict__ S, int n)
{
    const int tid = threadIdx.x;
    float* p = S + (size_t)blockIdx.x * n;

    __shared__ float red[256];

    float m = -INFINITY;
    for (int i = tid; i < n; i += 256) m = fmaxf(m, p[i]);
    red[tid] = m;
    __syncthreads();
    for (int s = 128; s > 0; s >>= 1) {
        if (tid < s) red[tid] = fmaxf(red[tid], red[tid + s]);
        __syncthreads();
    }
    m = red[0];
    __syncthreads();

    float sum = 0.0f;
    for (int i = tid; i < n; i += 256) {
        float e = __expf(p[i] - m);
        p[i] = e;
        sum += e;
    }
    red[tid] = sum;
    __syncthreads();
    for (int s = 128; s > 0; s >>= 1) {
        if (tid < s) red[tid] += red[tid + s];
        __syncthreads();
    }
    const float inv = 1.0f / red[0];
    __syncthreads();

    for (int i = tid; i < n; i += 256) p[i] *= inv;
}

// ---------------------------------------------------------------------------
extern "C" void kernel_launch(void* const* d_in, const int* in_sizes, int n_in,
                              void* d_out, int out_size)
{
    const float* X  = (const float*)d_in[0];
    const float* Wq = (const float*)d_in[1];
    const float* Wk = (const float*)d_in[2];
    const float* Wv = (const float*)d_in[3];
    const float* bq = (const float*)d_in[4];
    const float* bk = (const float*)d_in[5];
    const float* bv = (const float*)d_in[6];
    float* Out = (float*)d_out;

    float *Q, *K, *V, *S;
    cudaGetSymbolAddress((void**)&Q, g_Q);
    cudaGetSymbolAddress((void**)&K, g_K);
    cudaGetSymbolAddress((void**)&V, g_V);
    cudaGetSymbolAddress((void**)&S, g_S);

    const dim3 threads(256);
    const float scale = 0.03125f;  // 1/sqrt(1024)

    // Stage 1: Q/K/V = X @ W + b   (M=16384, N=1024, K=1024)
    {
        dim3 grid(DIM / 128, MTOT / 128, 1);
        mma_gemm<0><<<grid, threads>>>(X, Wq, Q, bq, MTOT, DIM, DIM, 0, 0, 0, 1.0f);
        mma_gemm<0><<<grid, threads>>>(X, Wk, K, bk, MTOT, DIM, DIM, 0, 0, 0, 1.0f);
        mma_gemm<0><<<grid, threads>>>(X, Wv, V, bv, MTOT, DIM, DIM, 0, 0, 0, 1.0f);
    }

    // Stage 2: S_b = scale * Q_b @ K_b^T   (per batch: M=4096, N=4096, K=1024)
    {
        dim3 grid(SEQ / 128, SEQ / 128, BATCH);
        mma_gemm<1><<<grid, threads>>>(
            Q, K, S, nullptr, SEQ, SEQ, DIM,
            (long long)SEQ * DIM, (long long)SEQ * DIM, (long long)SEQ * SEQ,
            scale);
    }

    // Stage 3: softmax over last dim of S
    softmax_rows_kernel<<<BATCH * SEQ, threads>>>(S, SEQ);

    // Stage 4: Out_b = P_b @ V_b   (per batch: M=4096, N=1024, K=4096)
    {
        dim3 grid(DIM / 128, SEQ / 128, BATCH);
        mma_gemm<0><<<grid, threads>>>(
            S, V, Out, nullptr, SEQ, DIM, SEQ,
            (long long)SEQ * SEQ, (long long)SEQ * DIM, (long long)SEQ * DIM,
            1.0f);
    }
}

// round 5
// speedup vs baseline: 2.5150x; 2.0254x over previous
#include <cuda_runtime.h>
#include <cuda_fp16.h>
#include <math.h>
#include <stdint.h>

static constexpr int BATCH = 4;
static constexpr int SEQ   = 4096;
static constexpr int DIM   = 1024;
static constexpr int MTOT  = BATCH * SEQ;   // 16384

// ---------------------------------------------------------------------------
// Scratch (device globals — no allocation allowed). All operands are stored as
// fp16 (hi, lo) splits; values pre-scaled so both hi and lo are fp16-normal.
// ---------------------------------------------------------------------------
__device__ __half g_Xh[(size_t)MTOT * DIM];
__device__ __half g_Xl[(size_t)MTOT * DIM];
__device__ __half g_Wqh[(size_t)DIM * DIM];   // W^T * 32
__device__ __half g_Wql[(size_t)DIM * DIM];
__device__ __half g_Wkh[(size_t)DIM * DIM];
__device__ __half g_Wkl[(size_t)DIM * DIM];
__device__ __half g_Wvh[(size_t)DIM * DIM];
__device__ __half g_Wvl[(size_t)DIM * DIM];
__device__ __half g_Qh[(size_t)MTOT * DIM];
__device__ __half g_Ql[(size_t)MTOT * DIM];
__device__ __half g_Kh[(size_t)MTOT * DIM];
__device__ __half g_Kl[(size_t)MTOT * DIM];
__device__ __half g_Vth[(size_t)DIM * MTOT];  // V^T: [e][b*SEQ+s]
__device__ __half g_Vtl[(size_t)DIM * MTOT];
__device__ float  g_S [(size_t)BATCH * SEQ * SEQ];
__device__ __half g_Ph[(size_t)BATCH * SEQ * SEQ];   // probs * 4096
__device__ __half g_Pl[(size_t)BATCH * SEQ * SEQ];

// ---------------------------------------------------------------------------
// PTX helpers
// ---------------------------------------------------------------------------
__device__ __forceinline__ uint32_t smem_u32(const void* p) {
    uint32_t a;
    asm("{ .reg .u64 t; cvta.to.shared.u64 t, %1; cvt.u32.u64 %0, t; }" : "=r"(a) : "l"(p));
    return a;
}
__device__ __forceinline__ void cp16(uint32_t saddr, const void* gaddr) {
    asm volatile("cp.async.cg.shared.global [%0], [%1], 16;\n" :: "r"(saddr), "l"(gaddr));
}
__device__ __forceinline__ void cp_commit() {
    asm volatile("cp.async.commit_group;\n" ::: "memory");
}
template <int N>
__device__ __forceinline__ void cp_wait() {
    asm volatile("cp.async.wait_group %0;\n" :: "n"(N) : "memory");
}
__device__ __forceinline__ void ldsm_x4(uint32_t* r, uint32_t addr) {
    asm volatile("ldmatrix.sync.aligned.m8n8.x4.shared.b16 {%0,%1,%2,%3}, [%4];"
                 : "=r"(r[0]), "=r"(r[1]), "=r"(r[2]), "=r"(r[3]) : "r"(addr));
}
__device__ __forceinline__ void mma_f16(float* d, const uint32_t* a, const uint32_t* b) {
    asm volatile(
        "mma.sync.aligned.m16n8k16.row.col.f32.f16.f16.f32 "
        "{%0,%1,%2,%3}, {%4,%5,%6,%7}, {%8,%9}, {%0,%1,%2,%3};"
        : "+f"(d[0]), "+f"(d[1]), "+f"(d[2]), "+f"(d[3])
        : "r"(a[0]), "r"(a[1]), "r"(a[2]), "r"(a[3]), "r"(b[0]), "r"(b[1]));
}

// ---------------------------------------------------------------------------
// fp16x3 NT GEMM:  C = alpha * (Ah+Al) @ (Bh+Bl)^T  [+ bias]   (drops Al*Bl)
//   A: [M x Kd] row-major halves (lda). B: [Nc x Kd] K-major halves (ldb).
//   Tile 128x128, K-slab 32, 8 warps (warp tile 64x32), 3-stage cp.async.
//   EPI 0: C0 (float) = alpha*acc
//   EPI 1: v = alpha*acc + bias[col]; C0 = fp16(v), C1 = fp16(v - C0)  (halves)
//   EPI 2: same as 1, transposed store: C0[col*ldt + row]
// ---------------------------------------------------------------------------
static constexpr int STAGE_BYTES = 40960;   // 4 tiles x 128 rows x 40 halves x 2B
static constexpr int GEMM_SMEM   = 3 * STAGE_BYTES;   // 120 KB

template <int EPI>
__global__ __launch_bounds__(256)
void hgemm_nt(const __half* __restrict__ Ah, const __half* __restrict__ Al,
              const __half* __restrict__ Bh, const __half* __restrict__ Bl,
              void* __restrict__ C0v, void* __restrict__ C1v,
              const float* __restrict__ bias,
              int Nc, int lda, int ldb, int NS,
              long long sA, long long sB, long long sC,
              float alpha, long long ldt)
{
    extern __shared__ __align__(16) char smem[];
    const uint32_t sbase = smem_u32(smem);

    const int tid  = threadIdx.x;
    const int wid  = tid >> 5;
    const int lane = tid & 31;

    const long long z = blockIdx.z;
    Ah += z * sA; Al += z * sA;
    Bh += z * sB; Bl += z * sB;

    const int wm = (wid & 1) * 64;
    const int wn = (wid >> 1) * 32;
    const long long arow0 = (long long)blockIdx.y * 128;
    const long long bcol0 = (long long)blockIdx.x * 128;

    float acc[4][4][4];
#pragma unroll
    for (int i = 0; i < 4; i++)
#pragma unroll
        for (int j = 0; j < 4; j++)
#pragma unroll
            for (int k = 0; k < 4; k++) acc[i][j][k] = 0.0f;

    // ldmatrix base offsets (bytes) within a tile, per lane
    const uint32_t a_off = (uint32_t)(((wm + (lane & 15)) * 40 + ((lane >> 4) & 1) * 8) * 2);
    const uint32_t b_off = (uint32_t)(((wn + ((lane >> 4) << 3) + (lane & 7)) * 40
                                       + ((lane >> 3) & 1) * 8) * 2);

    auto load_stage = [&](int buf, int k0) {
        const uint32_t sb = sbase + (uint32_t)buf * STAGE_BYTES;
#pragma unroll
        for (int i = 0; i < 2; i++) {
            const int idx = tid + i * 256;       // 0..511
            const int r = idx >> 2;              // 0..127
            const int c = idx & 3;               // 0..3 (8-half chunks)
            const uint32_t so = (uint32_t)((r * 40 + c * 8) * 2);
            const size_t ga = (size_t)(arow0 + r) * lda + k0 + c * 8;
            const size_t gb = (size_t)(bcol0 + r) * ldb + k0 + c * 8;
            cp16(sb + so,          Ah + ga);
            cp16(sb + 10240 + so,  Al + ga);
            cp16(sb + 20480 + so,  Bh + gb);
            cp16(sb + 30720 + so,  Bl + gb);
        }
        cp_commit();
    };

    auto compute = [&](int buf) {
        const uint32_t sb = sbase + (uint32_t)buf * STAGE_BYTES;
#pragma unroll
        for (int kc = 0; kc < 2; kc++) {
            const uint32_t ko = (uint32_t)(kc * 32);   // 16 halves = 32 bytes
            uint32_t af[4][4], bh2[4][2], bl2[4][2];
            // A-hi frags
#pragma unroll
            for (int mt = 0; mt < 4; mt++)
                ldsm_x4(af[mt], sb + a_off + (uint32_t)(mt * 1280) + ko);
            // B-hi frags
#pragma unroll
            for (int np = 0; np < 2; np++) {
                uint32_t t[4];
                ldsm_x4(t, sb + 20480 + b_off + (uint32_t)(np * 1280) + ko);
                bh2[2 * np][0] = t[0]; bh2[2 * np][1] = t[1];
                bh2[2 * np + 1][0] = t[2]; bh2[2 * np + 1][1] = t[3];
            }
            // term 1: Ah * Bh
#pragma unroll
            for (int mt = 0; mt < 4; mt++)
#pragma unroll
                for (int nt = 0; nt < 4; nt++)
                    mma_f16(acc[mt][nt], af[mt], bh2[nt]);
            // B-lo frags; term 2: Ah * Bl
#pragma unroll
            for (int np = 0; np < 2; np++) {
                uint32_t t[4];
                ldsm_x4(t, sb + 30720 + b_off + (uint32_t)(np * 1280) + ko);
                bl2[2 * np][0] = t[0]; bl2[2 * np][1] = t[1];
                bl2[2 * np + 1][0] = t[2]; bl2[2 * np + 1][1] = t[3];
            }
#pragma unroll
            for (int mt = 0; mt < 4; mt++)
#pragma unroll
                for (int nt = 0; nt < 4; nt++)
                    mma_f16(acc[mt][nt], af[mt], bl2[nt]);
            // A-lo frags (reuse af); term 3: Al * Bh
#pragma unroll
            for (int mt = 0; mt < 4; mt++)
                ldsm_x4(af[mt], sb + 10240 + a_off + (uint32_t)(mt * 1280) + ko);
#pragma unroll
            for (int mt = 0; mt < 4; mt++)
#pragma unroll
                for (int nt = 0; nt < 4; nt++)
                    mma_f16(acc[mt][nt], af[mt], bh2[nt]);
        }
    };

    // 3-stage pipeline, one barrier per K-slab
    load_stage(0, 0);
    load_stage(1, 32);
    for (int s = 0; s < NS; s++) {
        if (s + 1 < NS) cp_wait<1>(); else cp_wait<0>();
        __syncthreads();
        if (s + 2 < NS) load_stage((s + 2) % 3, (s + 2) * 32);
        compute(s % 3);
    }

    // ------------------------- epilogue ------------------------------------
    const int rr = lane >> 2;
    const int cc = 2 * (lane & 3);
#pragma unroll
    for (int mt = 0; mt < 4; mt++) {
#pragma unroll
        for (int nt = 0; nt < 4; nt++) {
            const long long row = arow0 + wm + mt * 16 + rr;
            const long long col = bcol0 + wn + nt * 8 + cc;
            float v00 = acc[mt][nt][0] * alpha;
            float v01 = acc[mt][nt][1] * alpha;
            float v10 = acc[mt][nt][2] * alpha;
            float v11 = acc[mt][nt][3] * alpha;
            if (EPI == 0) {
                float* C0 = (float*)C0v + z * sC;
                float2 a0 = {v00, v01}, a1 = {v10, v11};
                *(float2*)(C0 + row * Nc + col)       = a0;
                *(float2*)(C0 + (row + 8) * Nc + col) = a1;
            } else {
                const float b0 = bias[col], b1 = bias[col + 1];
                v00 += b0; v01 += b1; v10 += b0; v11 += b1;
                __half h00 = __float2half_rn(v00), h01 = __float2half_rn(v01);
                __half h10 = __float2half_rn(v10), h11 = __float2half_rn(v11);
                __half l00 = __float2half_rn(v00 - __half2float(h00));
                __half l01 = __float2half_rn(v01 - __half2float(h01));
                __half l10 = __float2half_rn(v10 - __half2float(h10));
                __half l11 = __float2half_rn(v11 - __half2float(h11));
                __half* C0 = (__half*)C0v;
                __half* C1 = (__half*)C1v;
                if (EPI == 1) {
                    *(__half2*)(C0 + row * Nc + col)       = __halves2half2(h00, h01);
                    *(__half2*)(C0 + (row + 8) * Nc + col) = __halves2half2(h10, h11);
                    *(__half2*)(C1 + row * Nc + col)       = __halves2half2(l00, l01);
                    *(__half2*)(C1 + (row + 8) * Nc + col) = __halves2half2(l10, l11);
                } else {  // EPI == 2: transposed scatter
                    C0[col * ldt + row]           = h00;
                    C0[(col + 1) * ldt + row]     = h01;
                    C0[col * ldt + row + 8]       = h10;
                    C0[(col + 1) * ldt + row + 8] = h11;
                    C1[col * ldt + row]           = l00;
                    C1[(col + 1) * ldt + row]     = l01;
                    C1[col * ldt + row + 8]       = l10;
                    C1[(col + 1) * ldt + row + 8] = l11;
                }
            }
        }
    }
}

// ---------------------------------------------------------------------------
// Elementwise fp16 split of X (unscaled; X ~ N(0,1))
// ---------------------------------------------------------------------------
__global__ __launch_bounds__(256)
void split_x_kernel(const float* __restrict__ X, __half* __restrict__ H,
                    __half* __restrict__ L, size_t n2)
{
    const size_t stride = (size_t)gridDim.x * 256;
    for (size_t i = blockIdx.x * 256ull + threadIdx.x; i < n2; i += stride) {
        float2 x = ((const float2*)X)[i];
        __half h0 = __float2half_rn(x.x), h1 = __float2half_rn(x.y);
        __half l0 = __float2half_rn(x.x - __half2float(h0));
        __half l1 = __float2half_rn(x.y - __half2float(h1));
        ((__half2*)H)[i] = __halves2half2(h0, h1);
        ((__half2*)L)[i] = __halves2half2(l0, l1);
    }
}

// ---------------------------------------------------------------------------
// Transpose + scale(x32) + split: W [DIM x DIM] -> Wt halves (Wt = 32 * W^T)
// ---------------------------------------------------------------------------
__global__ __launch_bounds__(256)
void transpose_split_kernel(const float* __restrict__ W,
                            __half* __restrict__ Th, __half* __restrict__ Tl)
{
    __shared__ float tile[32][33];
    const int tx = threadIdx.x, ty = threadIdx.y;   // 32 x 8
    const int x0 = blockIdx.x * 32, y0 = blockIdx.y * 32;
#pragma unroll
    for (int i = 0; i < 32; i += 8)
        tile[ty + i][tx] = W[(size_t)(y0 + ty + i) * DIM + x0 + tx];
    __syncthreads();
#pragma unroll
    for (int i = 0; i < 32; i += 8) {
        float v = tile[tx][ty + i] * 32.0f;
        __half h = __float2half_rn(v);
        __half l = __float2half_rn(v - __half2float(h));
        const size_t o = (size_t)(x0 + ty + i) * DIM + y0 + tx;
        Th[o] = h;
        Tl[o] = l;
    }
}

// ---------------------------------------------------------------------------
// Softmax rows of S -> fp16 split of 4096*probs. One block per row (n=4096).
// ---------------------------------------------------------------------------
__global__ __launch_bounds__(256)
void softmax_split_kernel(const float* __restrict__ S,
                          __half* __restrict__ Ph, __half* __restrict__ Pl)
{
    __shared__ float buf[SEQ];
    __shared__ float red[256];
    const int tid = threadIdx.x;
    const size_t off = (size_t)blockIdx.x * SEQ;

    float m = -INFINITY;
    for (int i = tid * 4; i < SEQ; i += 1024) {
        float4 v = *(const float4*)(S + off + i);
        *(float4*)(buf + i) = v;
        m = fmaxf(m, fmaxf(fmaxf(v.x, v.y), fmaxf(v.z, v.w)));
    }
    red[tid] = m;
    __syncthreads();
    for (int s = 128; s > 0; s >>= 1) {
        if (tid < s) red[tid] = fmaxf(red[tid], red[tid + s]);
        __syncthreads();
    }
    m = red[0];
    __syncthreads();

    float sum = 0.0f;
    for (int i = tid; i < SEQ; i += 256) {
        float e = __expf(buf[i] - m);
        buf[i] = e;
        sum += e;
    }
    red[tid] = sum;
    __syncthreads();
    for (int s = 128; s > 0; s >>= 1) {
        if (tid < s) red[tid] += red[tid + s];
        __syncthreads();
    }
    const float inv = 4096.0f / red[0];   // scale probs by 4096 (undone by alpha)
    __syncthreads();

    for (int i = tid; i < SEQ; i += 256) {
        float v = buf[i] * inv;
        __half h = __float2half_rn(v);
        Ph[off + i] = h;
        Pl[off + i] = __float2half_rn(v - __half2float(h));
    }
}

// ---------------------------------------------------------------------------
extern "C" void kernel_launch(void* const* d_in, const int* in_sizes, int n_in,
                              void* d_out, int out_size)
{
    const float* X  = (const float*)d_in[0];
    const float* Wq = (const float*)d_in[1];
    const float* Wk = (const float*)d_in[2];
    const float* Wv = (const float*)d_in[3];
    const float* bq = (const float*)d_in[4];
    const float* bk = (const float*)d_in[5];
    const float* bv = (const float*)d_in[6];
    float* Out = (float*)d_out;

    __half *Xh, *Xl, *Wqh, *Wql, *Wkh, *Wkl, *Wvh, *Wvl;
    __half *Qh, *Ql, *Kh, *Kl, *Vth, *Vtl, *Ph, *Pl;
    float* S;
    cudaGetSymbolAddress((void**)&Xh, g_Xh);   cudaGetSymbolAddress((void**)&Xl, g_Xl);
    cudaGetSymbolAddress((void**)&Wqh, g_Wqh); cudaGetSymbolAddress((void**)&Wql, g_Wql);
    cudaGetSymbolAddress((void**)&Wkh, g_Wkh); cudaGetSymbolAddress((void**)&Wkl, g_Wkl);
    cudaGetSymbolAddress((void**)&Wvh, g_Wvh); cudaGetSymbolAddress((void**)&Wvl, g_Wvl);
    cudaGetSymbolAddress((void**)&Qh, g_Qh);   cudaGetSymbolAddress((void**)&Ql, g_Ql);
    cudaGetSymbolAddress((void**)&Kh, g_Kh);   cudaGetSymbolAddress((void**)&Kl, g_Kl);
    cudaGetSymbolAddress((void**)&Vth, g_Vth); cudaGetSymbolAddress((void**)&Vtl, g_Vtl);
    cudaGetSymbolAddress((void**)&S, g_S);
    cudaGetSymbolAddress((void**)&Ph, g_Ph);   cudaGetSymbolAddress((void**)&Pl, g_Pl);

    cudaFuncSetAttribute(hgemm_nt<0>, cudaFuncAttributeMaxDynamicSharedMemorySize, GEMM_SMEM);
    cudaFuncSetAttribute(hgemm_nt<1>, cudaFuncAttributeMaxDynamicSharedMemorySize, GEMM_SMEM);
    cudaFuncSetAttribute(hgemm_nt<2>, cudaFuncAttributeMaxDynamicSharedMemorySize, GEMM_SMEM);

    // 0) operand splits
    split_x_kernel<<<2048, 256>>>(X, Xh, Xl, (size_t)MTOT * DIM / 2);
    {
        dim3 g(DIM / 32, DIM / 32), b(32, 8);
        transpose_split_kernel<<<g, b>>>(Wq, Wqh, Wql);
        transpose_split_kernel<<<g, b>>>(Wk, Wkh, Wkl);
        transpose_split_kernel<<<g, b>>>(Wv, Wvh, Wvl);
    }

    // 1) projections (alpha = 1/32 undoes W scaling), split epilogues
    {
        dim3 grid(DIM / 128, MTOT / 128, 1);
        hgemm_nt<1><<<grid, 256, GEMM_SMEM>>>(Xh, Xl, Wqh, Wql, Qh, Ql, bq,
                                              DIM, DIM, DIM, DIM / 32,
                                              0, 0, 0, 1.0f / 32.0f, 0);
        hgemm_nt<1><<<grid, 256, GEMM_SMEM>>>(Xh, Xl, Wkh, Wkl, Kh, Kl, bk,
                                              DIM, DIM, DIM, DIM / 32,
                                              0, 0, 0, 1.0f / 32.0f, 0);
        hgemm_nt<2><<<grid, 256, GEMM_SMEM>>>(Xh, Xl, Wvh, Wvl, Vth, Vtl, bv,
                                              DIM, DIM, DIM, DIM / 32,
                                              0, 0, 0, 1.0f / 32.0f, (long long)MTOT);
    }

    // 2) scores: S_b = (1/32) * Q_b @ K_b^T  (fp32 out)
    {
        dim3 grid(SEQ / 128, SEQ / 128, BATCH);
        hgemm_nt<0><<<grid, 256, GEMM_SMEM>>>(Qh, Ql, Kh, Kl, S, nullptr, nullptr,
                                              SEQ, DIM, DIM, DIM / 32,
                                              (long long)SEQ * DIM, (long long)SEQ * DIM,
                                              (long long)SEQ * SEQ, 0.03125f, 0);
    }

    // 3) softmax + split (probs * 4096)
    softmax_split_kernel<<<BATCH * SEQ, 256>>>(S, Ph, Pl);

    // 4) out: Out_b = (1/4096) * P4096_b @ Vt^T  (fp32 out)
    {
        dim3 grid(DIM / 128, SEQ / 128, BATCH);
        hgemm_nt<0><<<grid, 256, GEMM_SMEM>>>(Ph, Pl, Vth, Vtl, Out, nullptr, nullptr,
                                              DIM, SEQ, MTOT, SEQ / 32,
                                              (long long)SEQ * SEQ, (long long)SEQ,
                                              (long long)SEQ * DIM, 1.0f / 4096.0f, 0);
    }
}

// round 6
// speedup vs baseline: 3.4717x; 1.3804x over previous
#include <cuda_runtime.h>
#include <cuda_fp16.h>
#include <math.h>
#include <stdint.h>

static constexpr int BATCH = 4;
static constexpr int SEQ   = 4096;
static constexpr int DIM   = 1024;
static constexpr int MTOT  = BATCH * SEQ;   // 16384

// ---------------------------------------------------------------------------
// Scratch (device globals — no allocation allowed).
// A-operands are (hi, lo) fp16 pairs; B-operands single fp16 (pre-scaled).
// ---------------------------------------------------------------------------
__device__ __half g_Xh[(size_t)MTOT * DIM];
__device__ __half g_Xl[(size_t)MTOT * DIM];
__device__ __half g_Wqt[(size_t)DIM * DIM];   // W^T * 32, fp16
__device__ __half g_Wkt[(size_t)DIM * DIM];
__device__ __half g_Wvt[(size_t)DIM * DIM];
__device__ __half g_Qh[(size_t)MTOT * DIM];
__device__ __half g_Ql[(size_t)MTOT * DIM];
__device__ __half g_Ks[(size_t)MTOT * DIM];   // K single fp16
__device__ __half g_Vt[(size_t)DIM * MTOT];   // V^T single fp16: [e][b*SEQ+s]
__device__ float  g_S [(size_t)BATCH * SEQ * SEQ];
__device__ __half g_Ph[(size_t)BATCH * SEQ * SEQ];   // probs * 4096, split
__device__ __half g_Pl[(size_t)BATCH * SEQ * SEQ];

// ---------------------------------------------------------------------------
// PTX helpers
// ---------------------------------------------------------------------------
__device__ __forceinline__ uint32_t smem_u32(const void* p) {
    uint32_t a;
    asm("{ .reg .u64 t; cvta.to.shared.u64 t, %1; cvt.u32.u64 %0, t; }" : "=r"(a) : "l"(p));
    return a;
}
__device__ __forceinline__ void cp16(uint32_t saddr, const void* gaddr) {
    asm volatile("cp.async.cg.shared.global [%0], [%1], 16;\n" :: "r"(saddr), "l"(gaddr));
}
__device__ __forceinline__ void cp_commit() {
    asm volatile("cp.async.commit_group;\n" ::: "memory");
}
template <int N>
__device__ __forceinline__ void cp_wait() {
    asm volatile("cp.async.wait_group %0;\n" :: "n"(N) : "memory");
}
__device__ __forceinline__ void ldsm_x4(uint32_t* r, uint32_t addr) {
    asm volatile("ldmatrix.sync.aligned.m8n8.x4.shared.b16 {%0,%1,%2,%3}, [%4];"
                 : "=r"(r[0]), "=r"(r[1]), "=r"(r[2]), "=r"(r[3]) : "r"(addr));
}
__device__ __forceinline__ void mma_f16(float* d, const uint32_t* a, const uint32_t* b) {
    asm volatile(
        "mma.sync.aligned.m16n8k16.row.col.f32.f16.f16.f32 "
        "{%0,%1,%2,%3}, {%4,%5,%6,%7}, {%8,%9}, {%0,%1,%2,%3};"
        : "+f"(d[0]), "+f"(d[1]), "+f"(d[2]), "+f"(d[3])
        : "r"(a[0]), "r"(a[1]), "r"(a[2]), "r"(a[3]), "r"(b[0]), "r"(b[1]));
}

// ---------------------------------------------------------------------------
// fp16x2 NT GEMM:  C = alpha * (Ah+Al) @ B^T  [+ bias]
//   A: [M x Kd] row-major fp16 halves (lda). B: [Nc x Kd] K-major fp16 (ldb).
//   Tile 128x128, K-slab 32, 8 warps (warp tile 64x32), 4-stage cp.async.
//   EPI 0: C0 (float) = alpha*acc                      (scores / final out)
//   EPI 1: v = alpha*acc + bias; C0 = fp16(v), C1 = fp16(v - C0)   (Q split)
//   EPI 2: v = alpha*acc + bias; C0[col*ldt + row] = fp16(v)       (Vt)
//   EPI 3: v = alpha*acc + bias; C0[row*Nc + col]  = fp16(v)       (K)
// ---------------------------------------------------------------------------
static constexpr int TILE_BYTES_S = 10240;   // 128 rows x 40 halves x 2B
static constexpr int STAGE_BYTES  = 3 * TILE_BYTES_S;   // Ah, Al, B
static constexpr int GEMM_SMEM    = 4 * STAGE_BYTES;    // 120 KB

template <int EPI>
__global__ __launch_bounds__(256)
void hgemm_nt(const __half* __restrict__ Ah, const __half* __restrict__ Al,
              const __half* __restrict__ Bs,
              void* __restrict__ C0v, void* __restrict__ C1v,
              const float* __restrict__ bias,
              int Nc, int lda, int ldb, int NS,
              long long sA, long long sB, long long sC,
              float alpha, long long ldt)
{
    extern __shared__ __align__(16) char smem[];
    const uint32_t sbase = smem_u32(smem);

    const int tid  = threadIdx.x;
    const int wid  = tid >> 5;
    const int lane = tid & 31;

    const long long z = blockIdx.z;
    Ah += z * sA; Al += z * sA;
    Bs += z * sB;

    const int wm = (wid & 1) * 64;
    const int wn = (wid >> 1) * 32;
    const long long arow0 = (long long)blockIdx.y * 128;
    const long long bcol0 = (long long)blockIdx.x * 128;

    float acc[4][4][4];
#pragma unroll
    for (int i = 0; i < 4; i++)
#pragma unroll
        for (int j = 0; j < 4; j++)
#pragma unroll
            for (int k = 0; k < 4; k++) acc[i][j][k] = 0.0f;

    // ldmatrix base offsets (bytes) within a tile, per lane
    const uint32_t a_off = (uint32_t)(((wm + (lane & 15)) * 40 + ((lane >> 4) & 1) * 8) * 2);
    const uint32_t b_off = (uint32_t)(((wn + ((lane >> 4) << 3) + (lane & 7)) * 40
                                       + ((lane >> 3) & 1) * 8) * 2);

    auto load_stage = [&](int buf, int k0) {
        const uint32_t sb = sbase + (uint32_t)buf * STAGE_BYTES;
#pragma unroll
        for (int i = 0; i < 2; i++) {
            const int idx = tid + i * 256;       // 0..511
            const int r = idx >> 2;              // 0..127
            const int c = idx & 3;               // 0..3 (8-half chunks)
            const uint32_t so = (uint32_t)((r * 40 + c * 8) * 2);
            const size_t ga = (size_t)(arow0 + r) * lda + k0 + c * 8;
            const size_t gb = (size_t)(bcol0 + r) * ldb + k0 + c * 8;
            cp16(sb + so,                     Ah + ga);
            cp16(sb + TILE_BYTES_S + so,      Al + ga);
            cp16(sb + 2 * TILE_BYTES_S + so,  Bs + gb);
        }
        cp_commit();
    };

    auto compute = [&](int buf) {
        const uint32_t sb = sbase + (uint32_t)buf * STAGE_BYTES;
#pragma unroll
        for (int kc = 0; kc < 2; kc++) {
            const uint32_t ko = (uint32_t)(kc * 32);   // 16 halves = 32 bytes
            uint32_t af[4][4], bf[4][2];
            // B frags
#pragma unroll
            for (int np = 0; np < 2; np++) {
                uint32_t t[4];
                ldsm_x4(t, sb + 2 * TILE_BYTES_S + b_off + (uint32_t)(np * 1280) + ko);
                bf[2 * np][0] = t[0];     bf[2 * np][1] = t[1];
                bf[2 * np + 1][0] = t[2]; bf[2 * np + 1][1] = t[3];
            }
            // A-hi frags; term 1
#pragma unroll
            for (int mt = 0; mt < 4; mt++)
                ldsm_x4(af[mt], sb + a_off + (uint32_t)(mt * 1280) + ko);
#pragma unroll
            for (int mt = 0; mt < 4; mt++)
#pragma unroll
                for (int nt = 0; nt < 4; nt++)
                    mma_f16(acc[mt][nt], af[mt], bf[nt]);
            // A-lo frags; term 2
#pragma unroll
            for (int mt = 0; mt < 4; mt++)
                ldsm_x4(af[mt], sb + TILE_BYTES_S + a_off + (uint32_t)(mt * 1280) + ko);
#pragma unroll
            for (int mt = 0; mt < 4; mt++)
#pragma unroll
                for (int nt = 0; nt < 4; nt++)
                    mma_f16(acc[mt][nt], af[mt], bf[nt]);
        }
    };

    // 4-stage pipeline; one barrier per K-slab covers data-ready + buffer-free
    load_stage(0, 0);
    load_stage(1, 32);
    load_stage(2, 64);
    for (int s = 0; s < NS; s++) {
        if (s + 2 < NS)      cp_wait<2>();
        else if (s + 1 < NS) cp_wait<1>();
        else                 cp_wait<0>();
        __syncthreads();
        if (s + 3 < NS) load_stage((s + 3) & 3, (s + 3) * 32);
        compute(s & 3);
    }

    // ------------------------- epilogue ------------------------------------
    const int rr = lane >> 2;
    const int cc = 2 * (lane & 3);
#pragma unroll
    for (int mt = 0; mt < 4; mt++) {
#pragma unroll
        for (int nt = 0; nt < 4; nt++) {
            const long long row = arow0 + wm + mt * 16 + rr;
            const long long col = bcol0 + wn + nt * 8 + cc;
            float v00 = acc[mt][nt][0] * alpha;
            float v01 = acc[mt][nt][1] * alpha;
            float v10 = acc[mt][nt][2] * alpha;
            float v11 = acc[mt][nt][3] * alpha;
            if (EPI == 0) {
                float* C0 = (float*)C0v + z * sC;
                float2 a0 = {v00, v01}, a1 = {v10, v11};
                *(float2*)(C0 + row * Nc + col)       = a0;
                *(float2*)(C0 + (row + 8) * Nc + col) = a1;
            } else {
                const float b0 = bias[col], b1 = bias[col + 1];
                v00 += b0; v01 += b1; v10 += b0; v11 += b1;
                __half h00 = __float2half_rn(v00), h01 = __float2half_rn(v01);
                __half h10 = __float2half_rn(v10), h11 = __float2half_rn(v11);
                __half* C0 = (__half*)C0v;
                if (EPI == 1) {
                    __half l00 = __float2half_rn(v00 - __half2float(h00));
                    __half l01 = __float2half_rn(v01 - __half2float(h01));
                    __half l10 = __float2half_rn(v10 - __half2float(h10));
                    __half l11 = __float2half_rn(v11 - __half2float(h11));
                    __half* C1 = (__half*)C1v;
                    *(__half2*)(C0 + row * Nc + col)       = __halves2half2(h00, h01);
                    *(__half2*)(C0 + (row + 8) * Nc + col) = __halves2half2(h10, h11);
                    *(__half2*)(C1 + row * Nc + col)       = __halves2half2(l00, l01);
                    *(__half2*)(C1 + (row + 8) * Nc + col) = __halves2half2(l10, l11);
                } else if (EPI == 2) {  // transposed single
                    C0[col * ldt + row]           = h00;
                    C0[(col + 1) * ldt + row]     = h01;
                    C0[col * ldt + row + 8]       = h10;
                    C0[(col + 1) * ldt + row + 8] = h11;
                } else {                // EPI == 3: row-major single
                    *(__half2*)(C0 + row * Nc + col)       = __halves2half2(h00, h01);
                    *(__half2*)(C0 + (row + 8) * Nc + col) = __halves2half2(h10, h11);
                }
            }
        }
    }
}

// ---------------------------------------------------------------------------
// Elementwise fp16 split of X
// ---------------------------------------------------------------------------
__global__ __launch_bounds__(256)
void split_x_kernel(const float* __restrict__ X, __half* __restrict__ H,
                    __half* __restrict__ L, size_t n2)
{
    const size_t stride = (size_t)gridDim.x * 256;
    for (size_t i = blockIdx.x * 256ull + threadIdx.x; i < n2; i += stride) {
        float2 x = ((const float2*)X)[i];
        __half h0 = __float2half_rn(x.x), h1 = __float2half_rn(x.y);
        __half l0 = __float2half_rn(x.x - __half2float(h0));
        __half l1 = __float2half_rn(x.y - __half2float(h1));
        ((__half2*)H)[i] = __halves2half2(h0, h1);
        ((__half2*)L)[i] = __halves2half2(l0, l1);
    }
}

// ---------------------------------------------------------------------------
// Transpose + scale(x32) + fp16 round: W [DIM x DIM] -> Wt = fp16(32 * W^T)
// ---------------------------------------------------------------------------
__global__ __launch_bounds__(256)
void transpose_round_kernel(const float* __restrict__ W, __half* __restrict__ T)
{
    __shared__ float tile[32][33];
    const int tx = threadIdx.x, ty = threadIdx.y;   // 32 x 8
    const int x0 = blockIdx.x * 32, y0 = blockIdx.y * 32;
#pragma unroll
    for (int i = 0; i < 32; i += 8)
        tile[ty + i][tx] = W[(size_t)(y0 + ty + i) * DIM + x0 + tx];
    __syncthreads();
#pragma unroll
    for (int i = 0; i < 32; i += 8)
        T[(size_t)(x0 + ty + i) * DIM + y0 + tx] =
            __float2half_rn(tile[tx][ty + i] * 32.0f);
}

// ---------------------------------------------------------------------------
// Softmax rows of S -> fp16 split of 4096*probs. One block per row (n=4096).
// ---------------------------------------------------------------------------
__global__ __launch_bounds__(256)
void softmax_split_kernel(const float* __restrict__ S,
                          __half* __restrict__ Ph, __half* __restrict__ Pl)
{
    __shared__ float buf[SEQ];
    __shared__ float red[256];
    const int tid = threadIdx.x;
    const size_t off = (size_t)blockIdx.x * SEQ;

    float m = -INFINITY;
    for (int i = tid * 4; i < SEQ; i += 1024) {
        float4 v = *(const float4*)(S + off + i);
        *(float4*)(buf + i) = v;
        m = fmaxf(m, fmaxf(fmaxf(v.x, v.y), fmaxf(v.z, v.w)));
    }
    red[tid] = m;
    __syncthreads();
    for (int s = 128; s > 0; s >>= 1) {
        if (tid < s) red[tid] = fmaxf(red[tid], red[tid + s]);
        __syncthreads();
    }
    m = red[0];
    __syncthreads();

    float sum = 0.0f;
    for (int i = tid; i < SEQ; i += 256) {
        float e = __expf(buf[i] - m);
        buf[i] = e;
        sum += e;
    }
    red[tid] = sum;
    __syncthreads();
    for (int s = 128; s > 0; s >>= 1) {
        if (tid < s) red[tid] += red[tid + s];
        __syncthreads();
    }
    const float inv = 4096.0f / red[0];   // probs * 4096 (undone by alpha)
    __syncthreads();

    for (int i = tid; i < SEQ; i += 256) {
        float v = buf[i] * inv;
        __half h = __float2half_rn(v);
        Ph[off + i] = h;
        Pl[off + i] = __float2half_rn(v - __half2float(h));
    }
}

// ---------------------------------------------------------------------------
extern "C" void kernel_launch(void* const* d_in, const int* in_sizes, int n_in,
                              void* d_out, int out_size)
{
    const float* X  = (const float*)d_in[0];
    const float* Wq = (const float*)d_in[1];
    const float* Wk = (const float*)d_in[2];
    const float* Wv = (const float*)d_in[3];
    const float* bq = (const float*)d_in[4];
    const float* bk = (const float*)d_in[5];
    const float* bv = (const float*)d_in[6];
    float* Out = (float*)d_out;

    __half *Xh, *Xl, *Wqt, *Wkt, *Wvt, *Qh, *Ql, *Ks, *Vt, *Ph, *Pl;
    float* S;
    cudaGetSymbolAddress((void**)&Xh, g_Xh);   cudaGetSymbolAddress((void**)&Xl, g_Xl);
    cudaGetSymbolAddress((void**)&Wqt, g_Wqt); cudaGetSymbolAddress((void**)&Wkt, g_Wkt);
    cudaGetSymbolAddress((void**)&Wvt, g_Wvt);
    cudaGetSymbolAddress((void**)&Qh, g_Qh);   cudaGetSymbolAddress((void**)&Ql, g_Ql);
    cudaGetSymbolAddress((void**)&Ks, g_Ks);   cudaGetSymbolAddress((void**)&Vt, g_Vt);
    cudaGetSymbolAddress((void**)&S, g_S);
    cudaGetSymbolAddress((void**)&Ph, g_Ph);   cudaGetSymbolAddress((void**)&Pl, g_Pl);

    cudaFuncSetAttribute(hgemm_nt<0>, cudaFuncAttributeMaxDynamicSharedMemorySize, GEMM_SMEM);
    cudaFuncSetAttribute(hgemm_nt<1>, cudaFuncAttributeMaxDynamicSharedMemorySize, GEMM_SMEM);
    cudaFuncSetAttribute(hgemm_nt<2>, cudaFuncAttributeMaxDynamicSharedMemorySize, GEMM_SMEM);
    cudaFuncSetAttribute(hgemm_nt<3>, cudaFuncAttributeMaxDynamicSharedMemorySize, GEMM_SMEM);

    // 0) operand prep
    split_x_kernel<<<2048, 256>>>(X, Xh, Xl, (size_t)MTOT * DIM / 2);
    {
        dim3 g(DIM / 32, DIM / 32), b(32, 8);
        transpose_round_kernel<<<g, b>>>(Wq, Wqt);
        transpose_round_kernel<<<g, b>>>(Wk, Wkt);
        transpose_round_kernel<<<g, b>>>(Wv, Wvt);
    }

    // 1) projections (alpha = 1/32 undoes W scaling)
    {
        dim3 grid(DIM / 128, MTOT / 128, 1);
        hgemm_nt<1><<<grid, 256, GEMM_SMEM>>>(Xh, Xl, Wqt, Qh, Ql, bq,
                                              DIM, DIM, DIM, DIM / 32,
                                              0, 0, 0, 1.0f / 32.0f, 0);
        hgemm_nt<3><<<grid, 256, GEMM_SMEM>>>(Xh, Xl, Wkt, Ks, nullptr, bk,
                                              DIM, DIM, DIM, DIM / 32,
                                              0, 0, 0, 1.0f / 32.0f, 0);
        hgemm_nt<2><<<grid, 256, GEMM_SMEM>>>(Xh, Xl, Wvt, Vt, nullptr, bv,
                                              DIM, DIM, DIM, DIM / 32,
                                              0, 0, 0, 1.0f / 32.0f, (long long)MTOT);
    }

    // 2) scores: S_b = (1/32) * Q_b @ K_b^T  (fp32 out)
    {
        dim3 grid(SEQ / 128, SEQ / 128, BATCH);
        hgemm_nt<0><<<grid, 256, GEMM_SMEM>>>(Qh, Ql, Ks, S, nullptr, nullptr,
                                              SEQ, DIM, DIM, DIM / 32,
                                              (long long)SEQ * DIM, (long long)SEQ * DIM,
                                              (long long)SEQ * SEQ, 0.03125f, 0);
    }

    // 3) softmax + split (probs * 4096)
    softmax_split_kernel<<<BATCH * SEQ, 256>>>(S, Ph, Pl);

    // 4) out: Out_b = (1/4096) * P4096_b @ Vt^T  (fp32 out)
    {
        dim3 grid(DIM / 128, SEQ / 128, BATCH);
        hgemm_nt<0><<<grid, 256, GEMM_SMEM>>>(Ph, Pl, Vt, Out, nullptr, nullptr,
                                              DIM, SEQ, MTOT, SEQ / 32,
                                              (long long)SEQ * SEQ, (long long)SEQ,
                                              (long long)SEQ * DIM, 1.0f / 4096.0f, 0);
    }
}

// round 8
// speedup vs baseline: 6.6633x; 1.9193x over previous
#include <cuda_runtime.h>
#include <cuda_fp16.h>
#include <math.h>
#include <stdint.h>

static constexpr int BATCH = 4;
static constexpr int SEQ   = 4096;
static constexpr int DIM   = 1024;
static constexpr int MTOT  = BATCH * SEQ;   // 16384

// ---------------------------------------------------------------------------
// Scratch (device globals — no allocation allowed). All fp16 single-rounded.
// ---------------------------------------------------------------------------
__device__ __half g_Xs[(size_t)MTOT * DIM];
__device__ __half g_Wqt[(size_t)DIM * DIM];   // W^T * 32
__device__ __half g_Wkt[(size_t)DIM * DIM];
__device__ __half g_Wvt[(size_t)DIM * DIM];
__device__ __half g_Qs[(size_t)MTOT * DIM];
__device__ __half g_Ks[(size_t)MTOT * DIM];
__device__ __half g_Vt[(size_t)DIM * MTOT];   // V^T: [e][b*SEQ+s]
__device__ float  g_S [(size_t)BATCH * SEQ * SEQ];
__device__ __half g_Ps[(size_t)BATCH * SEQ * SEQ];   // probs * 4096

// ---------------------------------------------------------------------------
// PTX helpers
// ---------------------------------------------------------------------------
__device__ __forceinline__ uint32_t smem_u32(const void* p) {
    uint32_t a;
    asm("{ .reg .u64 t; cvta.to.shared.u64 t, %1; cvt.u32.u64 %0, t; }" : "=r"(a) : "l"(p));
    return a;
}
__device__ __forceinline__ void cp16(uint32_t saddr, const void* gaddr) {
    asm volatile("cp.async.cg.shared.global [%0], [%1], 16;\n" :: "r"(saddr), "l"(gaddr));
}
__device__ __forceinline__ void cp_commit() {
    asm volatile("cp.async.commit_group;\n" ::: "memory");
}
template <int N>
__device__ __forceinline__ void cp_wait() {
    asm volatile("cp.async.wait_group %0;\n" :: "n"(N) : "memory");
}
__device__ __forceinline__ void ldsm_x4(uint32_t* r, uint32_t addr) {
    asm volatile("ldmatrix.sync.aligned.m8n8.x4.shared.b16 {%0,%1,%2,%3}, [%4];"
                 : "=r"(r[0]), "=r"(r[1]), "=r"(r[2]), "=r"(r[3]) : "r"(addr));
}
__device__ __forceinline__ void mma_f16(float* d, const uint32_t* a, const uint32_t* b) {
    asm volatile(
        "mma.sync.aligned.m16n8k16.row.col.f32.f16.f16.f32 "
        "{%0,%1,%2,%3}, {%4,%5,%6,%7}, {%8,%9}, {%0,%1,%2,%3};"
        : "+f"(d[0]), "+f"(d[1]), "+f"(d[2]), "+f"(d[3])
        : "r"(a[0]), "r"(a[1]), "r"(a[2]), "r"(a[3]), "r"(b[0]), "r"(b[1]));
}

// ---------------------------------------------------------------------------
// fp16 NT GEMM:  C = alpha * A @ B^T  [+ bias]
//   A: [M x Kd] row-major fp16 (lda). B: [Nc x Kd] K-major fp16 (ldb).
//   Tile 128x128, K-slab 32, 8 warps (warp tile 64x32), 4-stage cp.async.
//   EPI 0: C0 (float) = alpha*acc                      (scores / final out)
//   EPI 2: v = alpha*acc + bias; C0[col*ldt + row] = fp16(v)   (Vt)
//   EPI 3: v = alpha*acc + bias; C0[row*Nc + col]  = fp16(v)   (Q, K)
// ---------------------------------------------------------------------------
static constexpr int TILE_BYTES_S = 10240;   // 128 rows x 40 halves x 2B
static constexpr int STAGE_BYTES  = 2 * TILE_BYTES_S;   // A, B
static constexpr int GEMM_SMEM    = 4 * STAGE_BYTES;    // 80 KB

template <int EPI>
__global__ __launch_bounds__(256)
void hgemm_nt(const __half* __restrict__ As, const __half* __restrict__ Bs,
              void* __restrict__ C0v,
              const float* __restrict__ bias,
              int Nc, int lda, int ldb, int NS,
              long long sA, long long sB, long long sC,
              float alpha, long long ldt)
{
    extern __shared__ __align__(16) char smem[];
    const uint32_t sbase = smem_u32(smem);

    const int tid  = threadIdx.x;
    const int wid  = tid >> 5;
    const int lane = tid & 31;

    const long long z = blockIdx.z;
    As += z * sA;
    Bs += z * sB;

    const int wm = (wid & 1) * 64;
    const int wn = (wid >> 1) * 32;
    const long long arow0 = (long long)blockIdx.y * 128;
    const long long bcol0 = (long long)blockIdx.x * 128;

    float acc[4][4][4];
#pragma unroll
    for (int i = 0; i < 4; i++)
#pragma unroll
        for (int j = 0; j < 4; j++)
#pragma unroll
            for (int k = 0; k < 4; k++) acc[i][j][k] = 0.0f;

    // ldmatrix base offsets (bytes) within a tile, per lane
    const uint32_t a_off = (uint32_t)(((wm + (lane & 15)) * 40 + ((lane >> 4) & 1) * 8) * 2);
    const uint32_t b_off = (uint32_t)(((wn + ((lane >> 4) << 3) + (lane & 7)) * 40
                                       + ((lane >> 3) & 1) * 8) * 2);

    auto load_stage = [&](int buf, int k0) {
        const uint32_t sb = sbase + (uint32_t)buf * STAGE_BYTES;
#pragma unroll
        for (int i = 0; i < 2; i++) {
            const int idx = tid + i * 256;       // 0..511
            const int r = idx >> 2;              // 0..127
            const int c = idx & 3;               // 0..3 (8-half chunks)
            const uint32_t so = (uint32_t)((r * 40 + c * 8) * 2);
            cp16(sb + so,                As + (size_t)(arow0 + r) * lda + k0 + c * 8);
            cp16(sb + TILE_BYTES_S + so, Bs + (size_t)(bcol0 + r) * ldb + k0 + c * 8);
        }
        cp_commit();
    };

    auto compute = [&](int buf) {
        const uint32_t sb = sbase + (uint32_t)buf * STAGE_BYTES;
#pragma unroll
        for (int kc = 0; kc < 2; kc++) {
            const uint32_t ko = (uint32_t)(kc * 32);   // 16 halves = 32 bytes
            uint32_t af[4][4], bf[4][2];
#pragma unroll
            for (int np = 0; np < 2; np++) {
                uint32_t t[4];
                ldsm_x4(t, sb + TILE_BYTES_S + b_off + (uint32_t)(np * 1280) + ko);
                bf[2 * np][0] = t[0];     bf[2 * np][1] = t[1];
                bf[2 * np + 1][0] = t[2]; bf[2 * np + 1][1] = t[3];
            }
#pragma unroll
            for (int mt = 0; mt < 4; mt++)
                ldsm_x4(af[mt], sb + a_off + (uint32_t)(mt * 1280) + ko);
#pragma unroll
            for (int mt = 0; mt < 4; mt++)
#pragma unroll
                for (int nt = 0; nt < 4; nt++)
                    mma_f16(acc[mt][nt], af[mt], bf[nt]);
        }
    };

    // 4-stage pipeline; one barrier per K-slab
    load_stage(0, 0);
    load_stage(1, 32);
    load_stage(2, 64);
    for (int s = 0; s < NS; s++) {
        if (s + 2 < NS)      cp_wait<2>();
        else if (s + 1 < NS) cp_wait<1>();
        else                 cp_wait<0>();
        __syncthreads();
        if (s + 3 < NS) load_stage((s + 3) & 3, (s + 3) * 32);
        compute(s & 3);
    }

    // ------------------------- epilogue ------------------------------------
    const int rr = lane >> 2;
    const int cc = 2 * (lane & 3);
#pragma unroll
    for (int nt = 0; nt < 4; nt++) {
        const long long col = bcol0 + wn + nt * 8 + cc;
        float b0 = 0.0f, b1 = 0.0f;
        if (EPI != 0) { b0 = bias[col]; b1 = bias[col + 1]; }
#pragma unroll
        for (int mt = 0; mt < 4; mt++) {
            const long long row = arow0 + wm + mt * 16 + rr;
            float v00 = acc[mt][nt][0] * alpha;
            float v01 = acc[mt][nt][1] * alpha;
            float v10 = acc[mt][nt][2] * alpha;
            float v11 = acc[mt][nt][3] * alpha;
            if (EPI == 0) {
                float* C0 = (float*)C0v + z * sC;
                float2 a0 = {v00, v01}, a1 = {v10, v11};
                *(float2*)(C0 + row * Nc + col)       = a0;
                *(float2*)(C0 + (row + 8) * Nc + col) = a1;
            } else {
                v00 += b0; v01 += b1; v10 += b0; v11 += b1;
                __half h00 = __float2half_rn(v00), h01 = __float2half_rn(v01);
                __half h10 = __float2half_rn(v10), h11 = __float2half_rn(v11);
                __half* C0 = (__half*)C0v;
                if (EPI == 2) {       // transposed store (Vt)
                    C0[col * ldt + row]           = h00;
                    C0[(col + 1) * ldt + row]     = h01;
                    C0[col * ldt + row + 8]       = h10;
                    C0[(col + 1) * ldt + row + 8] = h11;
                } else {              // EPI == 3: row-major store (Q, K)
                    *(__half2*)(C0 + row * Nc + col)       = __halves2half2(h00, h01);
                    *(__half2*)(C0 + (row + 8) * Nc + col) = __halves2half2(h10, h11);
                }
            }
        }
    }
}

// ---------------------------------------------------------------------------
// Elementwise fp16 round of X
// ---------------------------------------------------------------------------
__global__ __launch_bounds__(256)
void round_x_kernel(const float* __restrict__ X, __half* __restrict__ H, size_t n2)
{
    const size_t stride = (size_t)gridDim.x * 256;
    for (size_t i = blockIdx.x * 256ull + threadIdx.x; i < n2; i += stride) {
        float2 x = ((const float2*)X)[i];
        ((__half2*)H)[i] = __halves2half2(__float2half_rn(x.x), __float2half_rn(x.y));
    }
}

// ---------------------------------------------------------------------------
// Transpose + scale(x32) + fp16 round: W [DIM x DIM] -> Wt = fp16(32 * W^T)
// ---------------------------------------------------------------------------
__global__ __launch_bounds__(256)
void transpose_round_kernel(const float* __restrict__ W, __half* __restrict__ T)
{
    __shared__ float tile[32][33];
    const int tx = threadIdx.x, ty = threadIdx.y;   // 32 x 8
    const int x0 = blockIdx.x * 32, y0 = blockIdx.y * 32;
#pragma unroll
    for (int i = 0; i < 32; i += 8)
        tile[ty + i][tx] = W[(size_t)(y0 + ty + i) * DIM + x0 + tx];
    __syncthreads();
#pragma unroll
    for (int i = 0; i < 32; i += 8)
        T[(size_t)(x0 + ty + i) * DIM + y0 + tx] =
            __float2half_rn(tile[tx][ty + i] * 32.0f);
}

// ---------------------------------------------------------------------------
// Softmax rows of S -> fp16 round of 4096*probs. One block per row (n=4096).
// ---------------------------------------------------------------------------
__global__ __launch_bounds__(256)
void softmax_round_kernel(const float* __restrict__ S, __half* __restrict__ P)
{
    __shared__ float buf[SEQ];
    __shared__ float red[256];
    const int tid = threadIdx.x;
    const size_t off = (size_t)blockIdx.x * SEQ;

    float m = -INFINITY;
    for (int i = tid * 4; i < SEQ; i += 1024) {
        float4 v = *(const float4*)(S + off + i);
        *(float4*)(buf + i) = v;
        m = fmaxf(m, fmaxf(fmaxf(v.x, v.y), fmaxf(v.z, v.w)));
    }
    red[tid] = m;
    __syncthreads();
    for (int s = 128; s > 0; s >>= 1) {
        if (tid < s) red[tid] = fmaxf(red[tid], red[tid + s]);
        __syncthreads();
    }
    m = red[0];
    __syncthreads();

    float sum = 0.0f;
    for (int i = tid; i < SEQ; i += 256) {
        float e = __expf(buf[i] - m);
        buf[i] = e;
        sum += e;
    }
    red[tid] = sum;
    __syncthreads();
    for (int s = 128; s > 0; s >>= 1) {
        if (tid < s) red[tid] += red[tid + s];
        __syncthreads();
    }
    const float inv = 4096.0f / red[0];   // probs * 4096 (undone by alpha)
    __syncthreads();

    for (int i = tid * 2; i < SEQ; i += 512) {
        float2 v = *(const float2*)(buf + i);
        *(__half2*)(P + off + i) =
            __halves2half2(__float2half_rn(v.x * inv), __float2half_rn(v.y * inv));
    }
}

// ---------------------------------------------------------------------------
extern "C" void kernel_launch(void* const* d_in, const int* in_sizes, int n_in,
                              void* d_out, int out_size)
{
    const float* X  = (const float*)d_in[0];
    const float* Wq = (const float*)d_in[1];
    const float* Wk = (const float*)d_in[2];
    const float* Wv = (const float*)d_in[3];
    const float* bq = (const float*)d_in[4];
    const float* bk = (const float*)d_in[5];
    const float* bv = (const float*)d_in[6];
    float* Out = (float*)d_out;

    __half *Xs, *Wqt, *Wkt, *Wvt, *Qs, *Ks, *Vt, *Ps;
    float* S;
    cudaGetSymbolAddress((void**)&Xs, g_Xs);
    cudaGetSymbolAddress((void**)&Wqt, g_Wqt); cudaGetSymbolAddress((void**)&Wkt, g_Wkt);
    cudaGetSymbolAddress((void**)&Wvt, g_Wvt);
    cudaGetSymbolAddress((void**)&Qs, g_Qs);   cudaGetSymbolAddress((void**)&Ks, g_Ks);
    cudaGetSymbolAddress((void**)&Vt, g_Vt);
    cudaGetSymbolAddress((void**)&S, g_S);
    cudaGetSymbolAddress((void**)&Ps, g_Ps);

    cudaFuncSetAttribute(hgemm_nt<0>, cudaFuncAttributeMaxDynamicSharedMemorySize, GEMM_SMEM);
    cudaFuncSetAttribute(hgemm_nt<2>, cudaFuncAttributeMaxDynamicSharedMemorySize, GEMM_SMEM);
    cudaFuncSetAttribute(hgemm_nt<3>, cudaFuncAttributeMaxDynamicSharedMemorySize, GEMM_SMEM);

    // 0) operand prep
    round_x_kernel<<<2048, 256>>>(X, Xs, (size_t)MTOT * DIM / 2);
    {
        dim3 g(DIM / 32, DIM / 32), b(32, 8);
        transpose_round_kernel<<<g, b>>>(Wq, Wqt);
        transpose_round_kernel<<<g, b>>>(Wk, Wkt);
        transpose_round_kernel<<<g, b>>>(Wv, Wvt);
    }

    // 1) projections (alpha = 1/32 undoes W scaling)
    {
        dim3 grid(DIM / 128, MTOT / 128, 1);
        hgemm_nt<3><<<grid, 256, GEMM_SMEM>>>(Xs, Wqt, Qs, bq,
                                              DIM, DIM, DIM, DIM / 32,
                                              0, 0, 0, 1.0f / 32.0f, 0);
        hgemm_nt<3><<<grid, 256, GEMM_SMEM>>>(Xs, Wkt, Ks, bk,
                                              DIM, DIM, DIM, DIM / 32,
                                              0, 0, 0, 1.0f / 32.0f, 0);
        hgemm_nt<2><<<grid, 256, GEMM_SMEM>>>(Xs, Wvt, Vt, bv,
                                              DIM, DIM, DIM, DIM / 32,
                                              0, 0, 0, 1.0f / 32.0f, (long long)MTOT);
    }

    // 2) scores: S_b = (1/32) * Q_b @ K_b^T  (fp32 out)
    {
        dim3 grid(SEQ / 128, SEQ / 128, BATCH);
        hgemm_nt<0><<<grid, 256, GEMM_SMEM>>>(Qs, Ks, S, nullptr,
                                              SEQ, DIM, DIM, DIM / 32,
                                              (long long)SEQ * DIM, (long long)SEQ * DIM,
                                              (long long)SEQ * SEQ, 0.03125f, 0);
    }

    // 3) softmax (probs * 4096, fp16)
    softmax_round_kernel<<<BATCH * SEQ, 256>>>(S, Ps);

    // 4) out: Out_b = (1/4096) * P4096_b @ Vt^T  (fp32 out)
    {
        dim3 grid(DIM / 128, SEQ / 128, BATCH);
        hgemm_nt<0><<<grid, 256, GEMM_SMEM>>>(Ps, Vt, Out, nullptr,
                                              DIM, SEQ, MTOT, SEQ / 32,
                                              (long long)SEQ * SEQ, (long long)SEQ,
                                              (long long)SEQ * DIM, 1.0f / 4096.0f, 0);
    }
}